// round 12
// baseline (speedup 1.0000x reference)
#include <cuda_runtime.h>

// LIF neuron scan: T=8, leaky integrate + threshold + reset-by-subtraction.
// x: [T, N] fp32, N = 32*128*32*32 = 4,194,304 (N4 = 1,048,576 float4s).
//
// R8 (final sweep point): converged HBM-bound streaming kernel.
// Kernel time is pinned at 35.9-36.9us (~5.9TB/s DRAM + ~54MB L2 write
// absorption) across batched loads, persistent grid, cache hints, 2-wide
// threads, 256/512-thread CTAs. Traffic (134MB read + 134MB fp32 write) is
// irreducible. This round probes the last untested grid point: 128-thread
// CTAs (8192 blocks) for finer work-stealing granularity / lower per-SM
// finish-time spread. Body = best-measured (pointer-bump, interleaved).

#define T_STEPS 8
#define N_ELEM  (32 * 128 * 32 * 32)
#define N4      (N_ELEM / 4)
#define THREADS 128

__global__ __launch_bounds__(THREADS) void lif_kernel(
    const float4* __restrict__ x,
    const float*  __restrict__ vth_ptr,
    float4*       __restrict__ out)
{
    int idx = blockIdx.x * THREADS + threadIdx.x;

    const float4* __restrict__ xp = x + idx;
    float4*       __restrict__ op = out + idx;

    // no-grad clamp: relu(Vth - bound) + bound
    float Vth = vth_ptr[0];
    Vth = fmaxf(Vth - 0.0005f, 0.0f) + 0.0005f;

    const float beta = 0.9512294531f;   // fp32 nearest to exp(-0.05)
    const float omb  = 1.0f - beta;
    const float thr  = 0.3f * Vth;      // ALPHA * Vth
    const float sval = Vth * 20.0f;     // Vth / DELTA_T

    float mx = 0.f, my = 0.f, mz = 0.f, mw = 0.f;

#pragma unroll
    for (int t = 0; t < T_STEPS; t++, xp += N4, op += N4) {
        float4 xt = *xp;

        mx = beta * mx + omb * xt.x;
        my = beta * my + omb * xt.y;
        mz = beta * mz + omb * xt.z;
        mw = beta * mw + omb * xt.w;

        float4 o;
        if (mx >= thr) { o.x = sval; mx -= Vth; } else { o.x = 0.f; }
        if (my >= thr) { o.y = sval; my -= Vth; } else { o.y = 0.f; }
        if (mz >= thr) { o.z = sval; mz -= Vth; } else { o.z = 0.f; }
        if (mw >= thr) { o.w = sval; mw -= Vth; } else { o.w = 0.f; }

        *op = o;
    }
}

extern "C" void kernel_launch(void* const* d_in, const int* in_sizes, int n_in,
                              void* d_out, int out_size) {
    const float4* x   = (const float4*)d_in[0];
    const float*  vth = (const float*)d_in[1];
    float4*       out = (float4*)d_out;

    lif_kernel<<<N4 / THREADS, THREADS>>>(x, vth, out);   // 8192 blocks x 128
}

// round 14
// speedup vs baseline: 1.0007x; 1.0007x over previous
#include <cuda_runtime.h>

// LIF neuron scan: T=8, leaky integrate + threshold + reset-by-subtraction.
// x: [T, N] fp32, N = 32*128*32*32 = 4,194,304 (N4 = 1,048,576 float4s).
//
// FINAL. HBM-bound streaming kernel at its measured plateau:
//   ncu kernel 35.9-36.9us <=> ~5.95TB/s DRAM (75% of spec) + ~54MB L2 write
//   absorption, for every unit-stride configuration with occupancy >= 59%.
// Swept and rejected with post-mortems: batched loads (occupancy trade),
// persistent grid (serialized iteration deps), 2-wide threads (coalescing
// break -> L1tex-bound), __ldcs/__stcs in all combinations (neutral/negative),
// CTA sizes 128/256/512 (flat). Traffic (134MB read + 134MB fp32 write) is
// algorithmically irreducible. Remaining wall-vs-kernel gap (~8-9us) is fixed
// harness/graph-replay overhead, not kernel-addressable.
//
// Config: best-measured kernel (35.9us): 4096 blocks x 256 threads,
// pointer-bump interleaved body, 32 regs, occ ~82%.

#define T_STEPS 8
#define N_ELEM  (32 * 128 * 32 * 32)
#define N4      (N_ELEM / 4)
#define THREADS 256

__global__ __launch_bounds__(THREADS) void lif_kernel(
    const float4* __restrict__ x,
    const float*  __restrict__ vth_ptr,
    float4*       __restrict__ out)
{
    int idx = blockIdx.x * THREADS + threadIdx.x;

    const float4* __restrict__ xp = x + idx;
    float4*       __restrict__ op = out + idx;

    // no-grad clamp: relu(Vth - bound) + bound
    float Vth = vth_ptr[0];
    Vth = fmaxf(Vth - 0.0005f, 0.0f) + 0.0005f;

    const float beta = 0.9512294531f;   // fp32 nearest to exp(-0.05)
    const float omb  = 1.0f - beta;
    const float thr  = 0.3f * Vth;      // ALPHA * Vth
    const float sval = Vth * 20.0f;     // Vth / DELTA_T

    float mx = 0.f, my = 0.f, mz = 0.f, mw = 0.f;

#pragma unroll
    for (int t = 0; t < T_STEPS; t++, xp += N4, op += N4) {
        float4 xt = *xp;

        mx = beta * mx + omb * xt.x;
        my = beta * my + omb * xt.y;
        mz = beta * mz + omb * xt.z;
        mw = beta * mw + omb * xt.w;

        float4 o;
        if (mx >= thr) { o.x = sval; mx -= Vth; } else { o.x = 0.f; }
        if (my >= thr) { o.y = sval; my -= Vth; } else { o.y = 0.f; }
        if (mz >= thr) { o.z = sval; mz -= Vth; } else { o.z = 0.f; }
        if (mw >= thr) { o.w = sval; mw -= Vth; } else { o.w = 0.f; }

        *op = o;
    }
}

extern "C" void kernel_launch(void* const* d_in, const int* in_sizes, int n_in,
                              void* d_out, int out_size) {
    const float4* x   = (const float4*)d_in[0];
    const float*  vth = (const float*)d_in[1];
    float4*       out = (float4*)d_out;

    lif_kernel<<<N4 / THREADS, THREADS>>>(x, vth, out);   // 4096 blocks x 256
}